// round 3
// baseline (speedup 1.0000x reference)
#include <cuda_runtime.h>
#include <math.h>

#define N_NODES 50000
#define E_MAX   800000
#define D_H 64

// Scratch (device globals -- no allocation allowed)
__device__ float g_p[N_NODES * D_H];      // x @ Wl
__device__ float g_base[N_NODES * D_H];   // x @ Wr + bl
__device__ float g_h[N_NODES * D_H];      // elu(...) -> next layer input
__device__ int   g_cnt[N_NODES];
__device__ float g_inv[N_NODES];
__device__ int   g_row[N_NODES + 1];      // CSR row offsets (by dst)
__device__ int   g_cursor[N_NODES];
__device__ int   g_csr[E_MAX];            // src indices grouped by dst
__device__ int   g_src[E_MAX];
__device__ int   g_dst[E_MAX];
__device__ int   g_is64;

// Detect whether edge_index is int64 or int32. For int64 values < 2^31,
// every odd 32-bit word is zero; for random int32 indices it is not.
__global__ void probe_kernel(const int* __restrict__ w) {
    if (threadIdx.x == 0 && blockIdx.x == 0) {
        int z = 1;
        for (int i = 1; i < 129; i += 2)
            if (w[i] != 0) { z = 0; break; }
        g_is64 = z;
    }
}

__global__ void convert_kernel(const int* __restrict__ w, int E) {
    int e = blockIdx.x * blockDim.x + threadIdx.x;
    if (e >= E) return;
    if (g_is64) {
        g_src[e] = w[2 * e];            // little-endian low word
        g_dst[e] = w[2 * (E + e)];
    } else {
        g_src[e] = w[e];
        g_dst[e] = w[E + e];
    }
}

__global__ void zero_cnt_kernel() {
    int i = blockIdx.x * blockDim.x + threadIdx.x;
    if (i < N_NODES) g_cnt[i] = 0;
}

__global__ void count_kernel(int E) {
    int e = blockIdx.x * blockDim.x + threadIdx.x;
    if (e < E) atomicAdd(&g_cnt[g_dst[e]], 1);
}

// Single block, 1024 threads: exclusive scan of g_cnt -> g_row, g_cursor, g_inv
__global__ void scan_kernel() {
    __shared__ int sums[1024];
    int t = threadIdx.x;
    const int CH = (N_NODES + 1023) / 1024;
    int begin = t * CH;
    int end = begin + CH; if (end > N_NODES) end = N_NODES;
    int s = 0;
    for (int i = begin; i < end; i++) s += g_cnt[i];
    sums[t] = s;
    __syncthreads();
    for (int off = 1; off < 1024; off <<= 1) {
        int v = (t >= off) ? sums[t - off] : 0;
        __syncthreads();
        sums[t] += v;
        __syncthreads();
    }
    int run = (t == 0) ? 0 : sums[t - 1];
    for (int i = begin; i < end; i++) {
        g_row[i] = run;
        g_cursor[i] = run;
        int c = g_cnt[i];
        run += c;
        g_inv[i] = 1.0f / (float)(c > 1 ? c : 1);
    }
    if (t == 1023) g_row[N_NODES] = run;
}

__global__ void fill_kernel(int E) {
    int e = blockIdx.x * blockDim.x + threadIdx.x;
    if (e < E) {
        int pos = atomicAdd(&g_cursor[g_dst[e]], 1);
        g_csr[pos] = g_src[e];
    }
}

// out[r, c] = sum_k X[r,k] * W[k,c] (+ bias[c]).  W is [K,64] row-major.
// 2 threads per row, 32 cols each. W staged in shared.
__global__ void gemm_kernel(const float* __restrict__ X, const float* __restrict__ W,
                            const float* __restrict__ bias, float* __restrict__ out,
                            int N, int K) {
    __shared__ float Ws[128 * 64];
    for (int i = threadIdx.x; i < K * 64; i += blockDim.x) Ws[i] = W[i];
    __syncthreads();

    int t = blockIdx.x * blockDim.x + threadIdx.x;
    int row = t >> 1;
    int c0 = (t & 1) * 32;
    if (row >= N) return;

    const float* xr = X + (long)row * K;
    float acc[32];
#pragma unroll
    for (int c = 0; c < 32; c++) acc[c] = 0.0f;

    for (int k = 0; k < K; k += 4) {
        float4 xv = *(const float4*)(xr + k);
#pragma unroll
        for (int u = 0; u < 4; u++) {
            float xs = (&xv.x)[u];
            const float4* wr = (const float4*)(Ws + (k + u) * 64 + c0);
#pragma unroll
            for (int i = 0; i < 8; i++) {
                float4 w = wr[i];
                acc[i * 4 + 0] += xs * w.x;
                acc[i * 4 + 1] += xs * w.y;
                acc[i * 4 + 2] += xs * w.z;
                acc[i * 4 + 3] += xs * w.w;
            }
        }
    }
    if (bias) {
        const float* b = bias + c0;
#pragma unroll
        for (int c = 0; c < 32; c++) acc[c] += b[c];
    }
    float4* o = (float4*)(out + row * 64 + c0);
#pragma unroll
    for (int i = 0; i < 8; i++)
        o[i] = make_float4(acc[i * 4], acc[i * 4 + 1], acc[i * 4 + 2], acc[i * 4 + 3]);
}

// h[i] = elu(base[i] + inv[i] * sum_{j in N(i)} p[j]) — one warp per node,
// lane handles 2 floats (float2), neighbor rows read coalesced (256B/row).
__global__ void gather_elu_kernel() {
    int w = (blockIdx.x * blockDim.x + threadIdx.x) >> 5;
    if (w >= N_NODES) return;
    int lane = threadIdx.x & 31;
    int beg = g_row[w], end = g_row[w + 1];

    const float2* P = (const float2*)g_p;
    float ax = 0.0f, ay = 0.0f;
    int j = beg;
    for (; j + 1 < end; j += 2) {
        int s0 = g_csr[j], s1 = g_csr[j + 1];
        float2 v0 = P[s0 * 32 + lane];
        float2 v1 = P[s1 * 32 + lane];
        ax += v0.x + v1.x;
        ay += v0.y + v1.y;
    }
    if (j < end) {
        float2 v = P[g_csr[j] * 32 + lane];
        ax += v.x; ay += v.y;
    }
    float inv = g_inv[w];
    float2 b = ((const float2*)g_base)[w * 32 + lane];
    float vx = b.x + inv * ax;
    float vy = b.y + inv * ay;
    vx = vx > 0.0f ? vx : expm1f(vx);
    vy = vy > 0.0f ? vy : expm1f(vy);
    ((float2*)g_h)[w * 32 + lane] = make_float2(vx, vy);
}

// out[e, :4] = h[src] @ Wp[0:64] + h[dst] @ Wp[64:128] + bp
__global__ void edge_out_kernel(const float* __restrict__ Wp,
                                const float* __restrict__ bp,
                                float* __restrict__ out, int E) {
    __shared__ float Ws[512];
    for (int i = threadIdx.x; i < 512; i += blockDim.x) Ws[i] = Wp[i];
    __syncthreads();

    int e = blockIdx.x * blockDim.x + threadIdx.x;
    if (e >= E) return;
    int src = g_src[e];
    int dst = g_dst[e];

    float a0 = bp[0], a1 = bp[1], a2 = bp[2], a3 = bp[3];
    const float4* hs = ((const float4*)g_h) + src * 16;
    const float4* hd = ((const float4*)g_h) + dst * 16;

#pragma unroll
    for (int i = 0; i < 16; i++) {
        float4 v = hs[i];
#pragma unroll
        for (int u = 0; u < 4; u++) {
            float x = (&v.x)[u];
            const float* w = Ws + (i * 4 + u) * 4;
            a0 += x * w[0]; a1 += x * w[1]; a2 += x * w[2]; a3 += x * w[3];
        }
    }
#pragma unroll
    for (int i = 0; i < 16; i++) {
        float4 v = hd[i];
#pragma unroll
        for (int u = 0; u < 4; u++) {
            float x = (&v.x)[u];
            const float* w = Ws + 256 + (i * 4 + u) * 4;
            a0 += x * w[0]; a1 += x * w[1]; a2 += x * w[2]; a3 += x * w[3];
        }
    }
    ((float4*)out)[e] = make_float4(a0, a1, a2, a3);
}

extern "C" void kernel_launch(void* const* d_in, const int* in_sizes, int n_in,
                              void* d_out, int out_size) {
    const float* x   = (const float*)d_in[0];
    const int*   eiw = (const int*)d_in[1];   // raw words; dtype probed on device
    const float* Wl1 = (const float*)d_in[2];
    const float* bl1 = (const float*)d_in[3];
    const float* Wr1 = (const float*)d_in[4];
    const float* Wl2 = (const float*)d_in[5];
    const float* bl2 = (const float*)d_in[6];
    const float* Wr2 = (const float*)d_in[7];
    const float* Wl3 = (const float*)d_in[8];
    const float* bl3 = (const float*)d_in[9];
    const float* Wr3 = (const float*)d_in[10];
    const float* Wp  = (const float*)d_in[11];
    const float* bp  = (const float*)d_in[12];
    float* out = (float*)d_out;

    int E = in_sizes[1] / 2;  // edge_index is [2, E]; element count is dtype-independent
    if (E > E_MAX) E = E_MAX;

    float* d_p;    cudaGetSymbolAddress((void**)&d_p,    g_p);
    float* d_base; cudaGetSymbolAddress((void**)&d_base, g_base);
    float* d_h;    cudaGetSymbolAddress((void**)&d_h,    g_h);

    const int TB = 256;
    int gN    = (N_NODES + TB - 1) / TB;
    int gE    = (E + TB - 1) / TB;
    int gGemm = (N_NODES * 2 + TB - 1) / TB;       // 2 threads per row
    int gGath = (N_NODES * 32 + TB - 1) / TB;      // 1 warp per node

    // Decode edge_index (int32 vs int64) into int32 src/dst arrays
    probe_kernel<<<1, 32>>>(eiw);
    convert_kernel<<<gE, TB>>>(eiw, E);

    // Build CSR (by dst) + inverse degree
    zero_cnt_kernel<<<gN, TB>>>();
    count_kernel<<<gE, TB>>>(E);
    scan_kernel<<<1, 1024>>>();
    fill_kernel<<<gE, TB>>>(E);

    // Layer 1 (K=128)
    gemm_kernel<<<gGemm, TB>>>(x, Wl1, nullptr, d_p, N_NODES, 128);
    gemm_kernel<<<gGemm, TB>>>(x, Wr1, bl1,     d_base, N_NODES, 128);
    gather_elu_kernel<<<gGath, TB>>>();

    // Layer 2 (K=64)
    gemm_kernel<<<gGemm, TB>>>(d_h, Wl2, nullptr, d_p, N_NODES, 64);
    gemm_kernel<<<gGemm, TB>>>(d_h, Wr2, bl2,     d_base, N_NODES, 64);
    gather_elu_kernel<<<gGath, TB>>>();

    // Layer 3 (K=64)
    gemm_kernel<<<gGemm, TB>>>(d_h, Wl3, nullptr, d_p, N_NODES, 64);
    gemm_kernel<<<gGemm, TB>>>(d_h, Wr3, bl3,     d_base, N_NODES, 64);
    gather_elu_kernel<<<gGath, TB>>>();

    // Edge MLP
    edge_out_kernel<<<gE, TB>>>(Wp, bp, out, E);
}

// round 4
// speedup vs baseline: 1.7644x; 1.7644x over previous
#include <cuda_runtime.h>
#include <math.h>

#define N_NODES 50000
#define E_MAX   800000
#define D_H 64
#define NBLK 49   // ceil(50000/1024)

// Scratch (device globals -- no allocation allowed)
__device__ float g_p[N_NODES * D_H];      // x @ Wl
__device__ float g_base[N_NODES * D_H];   // x @ Wr + bl
__device__ float g_h[N_NODES * D_H];      // elu(...) -> next layer input
__device__ int   g_cnt[N_NODES];
__device__ float g_inv[N_NODES];
__device__ int   g_row[N_NODES + 1];      // CSR row offsets (by dst)
__device__ int   g_cursor[N_NODES];
__device__ int   g_csr[E_MAX];            // src indices grouped by dst
__device__ int   g_src[E_MAX];
__device__ int   g_dst[E_MAX];
__device__ int   g_is64;
__device__ int   g_bsum[NBLK];
__device__ int   g_boff[NBLK];

// Detect whether edge_index is int64 or int32. For int64 values < 2^31,
// every odd 32-bit word is zero; for random int32 indices it is not.
__global__ void probe_kernel(const int* __restrict__ w) {
    if (threadIdx.x == 0 && blockIdx.x == 0) {
        int z = 1;
        for (int i = 1; i < 129; i += 2)
            if (w[i] != 0) { z = 0; break; }
        g_is64 = z;
    }
}

__global__ void zero_cnt_kernel() {
    int i = blockIdx.x * blockDim.x + threadIdx.x;
    if (i < N_NODES) g_cnt[i] = 0;
}

// decode src/dst (+ count degrees) in one pass
__global__ void convert_count_kernel(const int* __restrict__ w, int E) {
    int e = blockIdx.x * blockDim.x + threadIdx.x;
    if (e >= E) return;
    int s, d;
    if (g_is64) { s = w[2 * e]; d = w[2 * (E + e)]; }
    else        { s = w[e];     d = w[E + e]; }
    g_src[e] = s;
    g_dst[e] = d;
    atomicAdd(&g_cnt[d], 1);
}

// phase 1: per-block sums of g_cnt (1024 nodes per block)
__global__ void blocksum_kernel() {
    __shared__ int s[1024];
    int t = threadIdx.x;
    int i = blockIdx.x * 1024 + t;
    int v = (i < N_NODES) ? g_cnt[i] : 0;
    s[t] = v;
    __syncthreads();
    for (int off = 512; off > 0; off >>= 1) {
        if (t < off) s[t] += s[t + off];
        __syncthreads();
    }
    if (t == 0) g_bsum[blockIdx.x] = s[0];
}

// phase 2: tiny exclusive scan of NBLK block sums (1 block, 64 threads)
__global__ void scan_bsum_kernel() {
    __shared__ int s[64];
    int t = threadIdx.x;
    int v = (t < NBLK) ? g_bsum[t] : 0;
    s[t] = v;
    __syncthreads();
    for (int off = 1; off < 64; off <<= 1) {
        int a = (t >= off) ? s[t - off] : 0;
        __syncthreads();
        s[t] += a;
        __syncthreads();
    }
    if (t < NBLK) g_boff[t] = s[t] - v;          // exclusive
    if (t == NBLK - 1) g_row[N_NODES] = s[t];    // total edges
}

// phase 3: block-local scan + global offset -> g_row, g_cursor, g_inv
__global__ void rowfill_kernel() {
    __shared__ int s[1024];
    int t = threadIdx.x;
    int i = blockIdx.x * 1024 + t;
    int v = (i < N_NODES) ? g_cnt[i] : 0;
    s[t] = v;
    __syncthreads();
    for (int off = 1; off < 1024; off <<= 1) {
        int a = (t >= off) ? s[t - off] : 0;
        __syncthreads();
        s[t] += a;
        __syncthreads();
    }
    if (i < N_NODES) {
        int excl = s[t] - v + g_boff[blockIdx.x];
        g_row[i] = excl;
        g_cursor[i] = excl;
        g_inv[i] = 1.0f / (float)(v > 1 ? v : 1);
    }
}

__global__ void fill_kernel(int E) {
    int e = blockIdx.x * blockDim.x + threadIdx.x;
    if (e < E) {
        int pos = atomicAdd(&g_cursor[g_dst[e]], 1);
        g_csr[pos] = g_src[e];
    }
}

// Fused dual GEMM: P = X @ Wl ; BASE = X @ Wr + bl.
// X: [N, K] row-major, Wl/Wr: [K, 64] row-major. Block computes 64 rows x 128
// combined cols (cols 0-63 -> P, 64-127 -> BASE). 128 threads, 8x8 register
// tile each: per k-step 4x LDS.128 feeds 64 FMA (1 B/FMA, FMA-pipe bound).
__global__ void __launch_bounds__(128) gemm2_kernel(
        const float* __restrict__ X,
        const float* __restrict__ Wl, const float* __restrict__ Wr,
        const float* __restrict__ bl,
        float* __restrict__ P, float* __restrict__ BASE,
        int N, int K) {
    __shared__ float Xs[16][64];
    __shared__ float Ws[16][128];
    int tid = threadIdx.x;
    int tx = tid & 15;       // col group (8 cols)
    int ty = tid >> 4;       // row group (8 rows)
    int row0 = blockIdx.x * 64;

    float acc[8][8];
#pragma unroll
    for (int i = 0; i < 8; i++)
#pragma unroll
        for (int j = 0; j < 8; j++) acc[i][j] = 0.0f;

    for (int k0 = 0; k0 < K; k0 += 16) {
        // stage X tile (64 rows x 16 k), transposed to Xs[k][row]
#pragma unroll
        for (int i = 0; i < 2; i++) {
            int f = tid + i * 128;       // 0..255 float4 slots
            int r = f >> 2;              // 0..63
            int kq = (f & 3) * 4;        // 0,4,8,12
            int grow = row0 + r;
            float4 v = make_float4(0.f, 0.f, 0.f, 0.f);
            if (grow < N) v = *(const float4*)(X + (long)grow * K + k0 + kq);
            Xs[kq + 0][r] = v.x; Xs[kq + 1][r] = v.y;
            Xs[kq + 2][r] = v.z; Xs[kq + 3][r] = v.w;
        }
        // stage combined W tile (16 k x 128 cols)
#pragma unroll
        for (int i = 0; i < 4; i++) {
            int f = tid + i * 128;       // 0..511 float4 slots
            int k = f >> 5;              // 0..15
            int c0 = (f & 31) * 4;       // 0..124
            const float* src = (c0 < 64) ? (Wl + (k0 + k) * 64 + c0)
                                         : (Wr + (k0 + k) * 64 + c0 - 64);
            *(float4*)&Ws[k][c0] = *(const float4*)src;
        }
        __syncthreads();
#pragma unroll
        for (int kk = 0; kk < 16; kk++) {
            float a[8], b[8];
            *(float4*)&a[0] = *(const float4*)&Xs[kk][ty * 8];
            *(float4*)&a[4] = *(const float4*)&Xs[kk][ty * 8 + 4];
            *(float4*)&b[0] = *(const float4*)&Ws[kk][tx * 8];
            *(float4*)&b[4] = *(const float4*)&Ws[kk][tx * 8 + 4];
#pragma unroll
            for (int i = 0; i < 8; i++)
#pragma unroll
                for (int j = 0; j < 8; j++) acc[i][j] += a[i] * b[j];
        }
        __syncthreads();
    }

    bool isP = (tx < 8);
    int c0 = (isP ? tx : tx - 8) * 8;
    float bias[8];
#pragma unroll
    for (int j = 0; j < 8; j++) bias[j] = isP ? 0.0f : bl[c0 + j];
    float* dstbuf = isP ? P : BASE;
#pragma unroll
    for (int i = 0; i < 8; i++) {
        int grow = row0 + ty * 8 + i;
        if (grow < N) {
            float4* o = (float4*)(dstbuf + grow * 64 + c0);
            o[0] = make_float4(acc[i][0] + bias[0], acc[i][1] + bias[1],
                               acc[i][2] + bias[2], acc[i][3] + bias[3]);
            o[1] = make_float4(acc[i][4] + bias[4], acc[i][5] + bias[5],
                               acc[i][6] + bias[6], acc[i][7] + bias[7]);
        }
    }
}

// h[i] = elu(base[i] + inv[i] * sum_{j in N(i)} p[j]) — one warp per node,
// lane handles 2 floats (float2), neighbor rows read coalesced (256B/row).
__global__ void gather_elu_kernel() {
    int w = (blockIdx.x * blockDim.x + threadIdx.x) >> 5;
    if (w >= N_NODES) return;
    int lane = threadIdx.x & 31;
    int beg = g_row[w], end = g_row[w + 1];

    const float2* P = (const float2*)g_p;
    float ax = 0.0f, ay = 0.0f;
    int j = beg;
    for (; j + 1 < end; j += 2) {
        int s0 = g_csr[j], s1 = g_csr[j + 1];
        float2 v0 = P[s0 * 32 + lane];
        float2 v1 = P[s1 * 32 + lane];
        ax += v0.x + v1.x;
        ay += v0.y + v1.y;
    }
    if (j < end) {
        float2 v = P[g_csr[j] * 32 + lane];
        ax += v.x; ay += v.y;
    }
    float inv = g_inv[w];
    float2 b = ((const float2*)g_base)[w * 32 + lane];
    float vx = b.x + inv * ax;
    float vy = b.y + inv * ay;
    vx = vx > 0.0f ? vx : expm1f(vx);
    vy = vy > 0.0f ? vy : expm1f(vy);
    ((float2*)g_h)[w * 32 + lane] = make_float2(vx, vy);
}

// out[e, :4] = h[src] @ Wp[0:64] + h[dst] @ Wp[64:128] + bp
__global__ void edge_out_kernel(const float* __restrict__ Wp,
                                const float* __restrict__ bp,
                                float* __restrict__ out, int E) {
    __shared__ float Ws[512];
    for (int i = threadIdx.x; i < 512; i += blockDim.x) Ws[i] = Wp[i];
    __syncthreads();

    int e = blockIdx.x * blockDim.x + threadIdx.x;
    if (e >= E) return;
    int src = g_src[e];
    int dst = g_dst[e];

    float a0 = bp[0], a1 = bp[1], a2 = bp[2], a3 = bp[3];
    const float4* hs = ((const float4*)g_h) + src * 16;
    const float4* hd = ((const float4*)g_h) + dst * 16;

#pragma unroll
    for (int i = 0; i < 16; i++) {
        float4 v = hs[i];
#pragma unroll
        for (int u = 0; u < 4; u++) {
            float x = (&v.x)[u];
            const float* w = Ws + (i * 4 + u) * 4;
            a0 += x * w[0]; a1 += x * w[1]; a2 += x * w[2]; a3 += x * w[3];
        }
    }
#pragma unroll
    for (int i = 0; i < 16; i++) {
        float4 v = hd[i];
#pragma unroll
        for (int u = 0; u < 4; u++) {
            float x = (&v.x)[u];
            const float* w = Ws + 256 + (i * 4 + u) * 4;
            a0 += x * w[0]; a1 += x * w[1]; a2 += x * w[2]; a3 += x * w[3];
        }
    }
    ((float4*)out)[e] = make_float4(a0, a1, a2, a3);
}

extern "C" void kernel_launch(void* const* d_in, const int* in_sizes, int n_in,
                              void* d_out, int out_size) {
    const float* x   = (const float*)d_in[0];
    const int*   eiw = (const int*)d_in[1];   // raw words; dtype probed on device
    const float* Wl1 = (const float*)d_in[2];
    const float* bl1 = (const float*)d_in[3];
    const float* Wr1 = (const float*)d_in[4];
    const float* Wl2 = (const float*)d_in[5];
    const float* bl2 = (const float*)d_in[6];
    const float* Wr2 = (const float*)d_in[7];
    const float* Wl3 = (const float*)d_in[8];
    const float* bl3 = (const float*)d_in[9];
    const float* Wr3 = (const float*)d_in[10];
    const float* Wp  = (const float*)d_in[11];
    const float* bp  = (const float*)d_in[12];
    float* out = (float*)d_out;

    int E = in_sizes[1] / 2;
    if (E > E_MAX) E = E_MAX;

    float* d_p;    cudaGetSymbolAddress((void**)&d_p,    g_p);
    float* d_base; cudaGetSymbolAddress((void**)&d_base, g_base);
    float* d_h;    cudaGetSymbolAddress((void**)&d_h,    g_h);

    const int TB = 256;
    int gN    = (N_NODES + TB - 1) / TB;
    int gE    = (E + TB - 1) / TB;
    int gGath = (N_NODES * 32 + TB - 1) / TB;      // 1 warp per node
    int gGemm = (N_NODES + 63) / 64;               // 64 rows per block

    // Decode edge_index + build CSR (by dst) + inverse degree
    probe_kernel<<<1, 32>>>(eiw);
    zero_cnt_kernel<<<gN, TB>>>();
    convert_count_kernel<<<gE, TB>>>(eiw, E);
    blocksum_kernel<<<NBLK, 1024>>>();
    scan_bsum_kernel<<<1, 64>>>();
    rowfill_kernel<<<NBLK, 1024>>>();
    fill_kernel<<<gE, TB>>>(E);

    // Layer 1 (K=128)
    gemm2_kernel<<<gGemm, 128>>>(x, Wl1, Wr1, bl1, d_p, d_base, N_NODES, 128);
    gather_elu_kernel<<<gGath, TB>>>();

    // Layer 2 (K=64)
    gemm2_kernel<<<gGemm, 128>>>(d_h, Wl2, Wr2, bl2, d_p, d_base, N_NODES, 64);
    gather_elu_kernel<<<gGath, TB>>>();

    // Layer 3 (K=64)
    gemm2_kernel<<<gGemm, 128>>>(d_h, Wl3, Wr3, bl3, d_p, d_base, N_NODES, 64);
    gather_elu_kernel<<<gGath, TB>>>();

    // Edge MLP
    edge_out_kernel<<<gE, TB>>>(Wp, bp, out, E);
}

// round 5
// speedup vs baseline: 1.8121x; 1.0270x over previous
#include <cuda_runtime.h>
#include <math.h>

#define N_NODES 50000
#define E_MAX   800000
#define D_H 64

// Scratch (device globals -- no allocation allowed)
__device__ float g_p[N_NODES * D_H];      // x @ Wl
__device__ float g_base[N_NODES * D_H];   // x @ Wr + bl
__device__ float g_h[N_NODES * D_H];      // elu(...) -> next layer input
__device__ int   g_cnt[N_NODES];
__device__ float g_inv[N_NODES];
__device__ int   g_row[N_NODES + 1];      // CSR row offsets (by dst)
__device__ int   g_cursor[N_NODES];
__device__ int   g_csr[E_MAX];            // src indices grouped by dst
__device__ int   g_src[E_MAX];
__device__ int   g_dst[E_MAX];
__device__ float4 g_a[N_NODES];           // h @ Wp_top + bp
__device__ float4 g_b[N_NODES];           // h @ Wp_bot

__global__ void zero_cnt_kernel() {
    int i = blockIdx.x * blockDim.x + threadIdx.x;
    if (i < N_NODES) g_cnt[i] = 0;
}

// decode src/dst (+ count degrees) in one pass. int64-vs-int32 detection is
// done per block from the first 128 words (all L2-broadcast): for int64
// indices < 2^31 every odd word is 0; for 64 random int32 indices it isn't.
__global__ void convert_count_kernel(const int* __restrict__ w, int E) {
    __shared__ int is64_s;
    if (threadIdx.x == 0) {
        int z = 1;
        for (int i = 1; i < 129; i += 2)
            if (w[i] != 0) { z = 0; break; }
        is64_s = z;
    }
    __syncthreads();
    int is64 = is64_s;
    int e = blockIdx.x * blockDim.x + threadIdx.x;
    if (e >= E) return;
    int s, d;
    if (is64) { s = w[2 * e]; d = w[2 * (E + e)]; }
    else      { s = w[e];     d = w[E + e]; }
    g_src[e] = s;
    g_dst[e] = d;
    atomicAdd(&g_cnt[d], 1);
}

// Single block, 1024 threads: exclusive scan of g_cnt -> g_row, g_cursor, g_inv
__global__ void scan_kernel() {
    __shared__ int sums[1024];
    int t = threadIdx.x;
    const int CH = (N_NODES + 1023) / 1024;
    int begin = t * CH;
    int end = begin + CH; if (end > N_NODES) end = N_NODES;
    int s = 0;
    for (int i = begin; i < end; i++) s += g_cnt[i];
    sums[t] = s;
    __syncthreads();
    for (int off = 1; off < 1024; off <<= 1) {
        int v = (t >= off) ? sums[t - off] : 0;
        __syncthreads();
        sums[t] += v;
        __syncthreads();
    }
    int run = (t == 0) ? 0 : sums[t - 1];
    for (int i = begin; i < end; i++) {
        g_row[i] = run;
        g_cursor[i] = run;
        int c = g_cnt[i];
        run += c;
        g_inv[i] = 1.0f / (float)(c > 1 ? c : 1);
    }
    if (t == 1023) g_row[N_NODES] = run;
}

__global__ void fill_kernel(int E) {
    int e = blockIdx.x * blockDim.x + threadIdx.x;
    if (e < E) {
        int pos = atomicAdd(&g_cursor[g_dst[e]], 1);
        g_csr[pos] = g_src[e];
    }
}

// Fused dual GEMM: P = X @ Wl ; BASE = X @ Wr + bl.
// Block computes 64 rows x 128 combined cols (0-63 -> P, 64-127 -> BASE).
// 128 threads, 8x8 register tile each: 4x LDS.128 per k feeds 64 FMA.
__global__ void __launch_bounds__(128) gemm2_kernel(
        const float* __restrict__ X,
        const float* __restrict__ Wl, const float* __restrict__ Wr,
        const float* __restrict__ bl,
        float* __restrict__ P, float* __restrict__ BASE,
        int N, int K) {
    __shared__ float Xs[16][64];
    __shared__ float Ws[16][128];
    int tid = threadIdx.x;
    int tx = tid & 15;       // col group (8 cols)
    int ty = tid >> 4;       // row group (8 rows)
    int row0 = blockIdx.x * 64;

    float acc[8][8];
#pragma unroll
    for (int i = 0; i < 8; i++)
#pragma unroll
        for (int j = 0; j < 8; j++) acc[i][j] = 0.0f;

    for (int k0 = 0; k0 < K; k0 += 16) {
#pragma unroll
        for (int i = 0; i < 2; i++) {
            int f = tid + i * 128;
            int r = f >> 2;
            int kq = (f & 3) * 4;
            int grow = row0 + r;
            float4 v = make_float4(0.f, 0.f, 0.f, 0.f);
            if (grow < N) v = *(const float4*)(X + (long)grow * K + k0 + kq);
            Xs[kq + 0][r] = v.x; Xs[kq + 1][r] = v.y;
            Xs[kq + 2][r] = v.z; Xs[kq + 3][r] = v.w;
        }
#pragma unroll
        for (int i = 0; i < 4; i++) {
            int f = tid + i * 128;
            int k = f >> 5;
            int c0 = (f & 31) * 4;
            const float* src = (c0 < 64) ? (Wl + (k0 + k) * 64 + c0)
                                         : (Wr + (k0 + k) * 64 + c0 - 64);
            *(float4*)&Ws[k][c0] = *(const float4*)src;
        }
        __syncthreads();
#pragma unroll
        for (int kk = 0; kk < 16; kk++) {
            float a[8], b[8];
            *(float4*)&a[0] = *(const float4*)&Xs[kk][ty * 8];
            *(float4*)&a[4] = *(const float4*)&Xs[kk][ty * 8 + 4];
            *(float4*)&b[0] = *(const float4*)&Ws[kk][tx * 8];
            *(float4*)&b[4] = *(const float4*)&Ws[kk][tx * 8 + 4];
#pragma unroll
            for (int i = 0; i < 8; i++)
#pragma unroll
                for (int j = 0; j < 8; j++) acc[i][j] += a[i] * b[j];
        }
        __syncthreads();
    }

    bool isP = (tx < 8);
    int c0 = (isP ? tx : tx - 8) * 8;
    float bias[8];
#pragma unroll
    for (int j = 0; j < 8; j++) bias[j] = isP ? 0.0f : bl[c0 + j];
    float* dstbuf = isP ? P : BASE;
#pragma unroll
    for (int i = 0; i < 8; i++) {
        int grow = row0 + ty * 8 + i;
        if (grow < N) {
            float4* o = (float4*)(dstbuf + grow * 64 + c0);
            o[0] = make_float4(acc[i][0] + bias[0], acc[i][1] + bias[1],
                               acc[i][2] + bias[2], acc[i][3] + bias[3]);
            o[1] = make_float4(acc[i][4] + bias[4], acc[i][5] + bias[5],
                               acc[i][6] + bias[6], acc[i][7] + bias[7]);
        }
    }
}

// h[i] = elu(base[i] + inv[i] * sum_{j in N(i)} p[j]) — one warp per node,
// lane handles 2 floats (float2), neighbor rows read coalesced (256B/row).
// PROJ: additionally a[i] = h[i]@Wp_top + bp, b[i] = h[i]@Wp_bot via warp
// shuffle reduction (Wp staged in shared).
template <bool PROJ>
__global__ void gather_elu_kernel(const float* __restrict__ Wp,
                                  const float* __restrict__ bp) {
    __shared__ float Ws[512];
    if (PROJ) {
        for (int i = threadIdx.x; i < 512; i += blockDim.x) Ws[i] = Wp[i];
        __syncthreads();
    }
    int w = (blockIdx.x * blockDim.x + threadIdx.x) >> 5;
    if (w >= N_NODES) return;
    int lane = threadIdx.x & 31;
    int beg = g_row[w], end = g_row[w + 1];

    const float2* P = (const float2*)g_p;
    float ax = 0.0f, ay = 0.0f;
    int j = beg;
    for (; j + 1 < end; j += 2) {
        int s0 = g_csr[j], s1 = g_csr[j + 1];
        float2 v0 = P[s0 * 32 + lane];
        float2 v1 = P[s1 * 32 + lane];
        ax += v0.x + v1.x;
        ay += v0.y + v1.y;
    }
    if (j < end) {
        float2 v = P[g_csr[j] * 32 + lane];
        ax += v.x; ay += v.y;
    }
    float inv = g_inv[w];
    float2 b = ((const float2*)g_base)[w * 32 + lane];
    float vx = b.x + inv * ax;
    float vy = b.y + inv * ay;
    vx = vx > 0.0f ? vx : expm1f(vx);
    vy = vy > 0.0f ? vy : expm1f(vy);
    ((float2*)g_h)[w * 32 + lane] = make_float2(vx, vy);

    if (PROJ) {
        // cols handled by this lane: c0 = 2*lane, c1 = 2*lane+1
        int c0 = 2 * lane;
        float sa[4], sb[4];
#pragma unroll
        for (int o = 0; o < 4; o++) {
            sa[o] = vx * Ws[c0 * 4 + o]        + vy * Ws[(c0 + 1) * 4 + o];
            sb[o] = vx * Ws[(64 + c0) * 4 + o] + vy * Ws[(64 + c0 + 1) * 4 + o];
        }
#pragma unroll
        for (int off = 16; off > 0; off >>= 1) {
#pragma unroll
            for (int o = 0; o < 4; o++) {
                sa[o] += __shfl_xor_sync(0xffffffffu, sa[o], off);
                sb[o] += __shfl_xor_sync(0xffffffffu, sb[o], off);
            }
        }
        if (lane == 0) {
            g_a[w] = make_float4(sa[0] + bp[0], sa[1] + bp[1],
                                 sa[2] + bp[2], sa[3] + bp[3]);
            g_b[w] = make_float4(sb[0], sb[1], sb[2], sb[3]);
        }
    }
}

// out[e] = a[src] + b[dst]
__global__ void edge_out_kernel(float* __restrict__ out, int E) {
    int e = blockIdx.x * blockDim.x + threadIdx.x;
    if (e >= E) return;
    float4 a = g_a[g_src[e]];
    float4 b = g_b[g_dst[e]];
    ((float4*)out)[e] = make_float4(a.x + b.x, a.y + b.y, a.z + b.z, a.w + b.w);
}

extern "C" void kernel_launch(void* const* d_in, const int* in_sizes, int n_in,
                              void* d_out, int out_size) {
    const float* x   = (const float*)d_in[0];
    const int*   eiw = (const int*)d_in[1];   // raw words; dtype probed on device
    const float* Wl1 = (const float*)d_in[2];
    const float* bl1 = (const float*)d_in[3];
    const float* Wr1 = (const float*)d_in[4];
    const float* Wl2 = (const float*)d_in[5];
    const float* bl2 = (const float*)d_in[6];
    const float* Wr2 = (const float*)d_in[7];
    const float* Wl3 = (const float*)d_in[8];
    const float* bl3 = (const float*)d_in[9];
    const float* Wr3 = (const float*)d_in[10];
    const float* Wp  = (const float*)d_in[11];
    const float* bp  = (const float*)d_in[12];
    float* out = (float*)d_out;

    int E = in_sizes[1] / 2;
    if (E > E_MAX) E = E_MAX;

    float* d_p;    cudaGetSymbolAddress((void**)&d_p,    g_p);
    float* d_base; cudaGetSymbolAddress((void**)&d_base, g_base);
    float* d_h;    cudaGetSymbolAddress((void**)&d_h,    g_h);

    const int TB = 256;
    int gN    = (N_NODES + TB - 1) / TB;
    int gE    = (E + TB - 1) / TB;
    int gGath = (N_NODES * 32 + TB - 1) / TB;      // 1 warp per node
    int gGemm = (N_NODES + 63) / 64;               // 64 rows per block

    // Decode edge_index + build CSR (by dst) + inverse degree
    zero_cnt_kernel<<<gN, TB>>>();
    convert_count_kernel<<<gE, TB>>>(eiw, E);
    scan_kernel<<<1, 1024>>>();
    fill_kernel<<<gE, TB>>>(E);

    // Layer 1 (K=128)
    gemm2_kernel<<<gGemm, 128>>>(x, Wl1, Wr1, bl1, d_p, d_base, N_NODES, 128);
    gather_elu_kernel<false><<<gGath, TB>>>(nullptr, nullptr);

    // Layer 2 (K=64)
    gemm2_kernel<<<gGemm, 128>>>(d_h, Wl2, Wr2, bl2, d_p, d_base, N_NODES, 64);
    gather_elu_kernel<false><<<gGath, TB>>>(nullptr, nullptr);

    // Layer 3 (K=64) + fused edge-MLP projection
    gemm2_kernel<<<gGemm, 128>>>(d_h, Wl3, Wr3, bl3, d_p, d_base, N_NODES, 64);
    gather_elu_kernel<true><<<gGath, TB>>>(Wp, bp);

    // out[e] = a[src] + b[dst]
    edge_out_kernel<<<gE, TB>>>(out, E);
}